// round 4
// baseline (speedup 1.0000x reference)
#include <cuda_runtime.h>
#include <cuda_fp16.h>
#include <cuda_bf16.h>
#include <cstdint>

// Problem constants (fixed by the reference).
constexpr int B = 8, C = 3, H = 720, W = 1280;
constexpr int HW = H * W;            // 921600
constexpr int NPIX = B * HW;         // 7372800
constexpr int CHW = C * HW;

// scratchA: per pixel, half2 = (ch0, ch1).        29.5 MB
// scratchB: per pixel PAIR, half2 = (ch2[2k], ch2[2k+1]).  14.7 MB
__device__ __align__(16) unsigned int g_sA[NPIX];
__device__ __align__(16) unsigned int g_sB[NPIX / 2];

__device__ __forceinline__ void red_add_f16x2(unsigned int* p, unsigned int v) {
    asm volatile("red.global.add.noftz.f16x2 [%0], %1;"
                 :: "l"(p), "r"(v) : "memory");
}
__device__ __forceinline__ void red_add_f16(__half* p, __half v) {
    unsigned short u = *reinterpret_cast<unsigned short*>(&v);
    asm volatile("red.global.add.noftz.f16 [%0], %1;"
                 :: "l"(p), "h"(u) : "memory");
}
__device__ __forceinline__ unsigned int pack2(float a, float b) {
    __half2 h = __floats2half2_rn(a, b);
    return *reinterpret_cast<unsigned int*>(&h);
}

// ---------------------------------------------------------------------------
// Pass 1: zero both scratch arrays (out is fully overwritten by finalize).
// ---------------------------------------------------------------------------
__global__ __launch_bounds__(256)
void zero_kernel() {
    constexpr int NA4 = NPIX / 4;          // uint4 count in g_sA
    constexpr int NB4 = NPIX / 8;          // uint4 count in g_sB
    int j = blockIdx.x * blockDim.x + threadIdx.x;
    if (j < NA4) {
        reinterpret_cast<uint4*>(g_sA)[j] = make_uint4(0u, 0u, 0u, 0u);
    } else if (j < NA4 + NB4) {
        reinterpret_cast<uint4*>(g_sB)[j - NA4] = make_uint4(0u, 0u, 0u, 0u);
    }
}

// ---------------------------------------------------------------------------
// Pass 2: forward-warp scatter. Per corner row-pair:
//   2x f16x2 RED into scratchA (ch0,ch1 per pixel)
//   ch2: 1x f16x2 into scratchB when the pair starts on an even pixel,
//        else scalar f16 REDs. Avg ~7 L2 atomic elements per source pixel.
// ---------------------------------------------------------------------------
__global__ __launch_bounds__(256)
void forward_warp_kernel(const float* __restrict__ im0,
                         const float2* __restrict__ flow) {
    int p = blockIdx.x * blockDim.x + threadIdx.x;
    if (p >= NPIX) return;

    int b = p / HW;
    int r = p - b * HW;
    int h = r / W;
    int w = r - h * W;

    float2 f = flow[p];
    float x = (float)w + f.x;
    float y = (float)h + f.y;

    float x0f = floorf(x);
    float y0f = floorf(y);
    float wx1 = x - x0f;
    float wx0 = 1.0f - wx1;
    float wy1 = y - y0f;
    float wy0 = 1.0f - wy1;

    int ibase = b * CHW + r;
    float v0 = im0[ibase];
    float v1 = im0[ibase + HW];
    float v2 = im0[ibase + 2 * HW];

    int xi = (int)x0f;
    bool lo_ok = (x0f >= 0.0f)  && (x0f <= (float)(W - 1));
    bool hi_ok = (x0f >= -1.0f) && (x0f <= (float)(W - 2));
    int pbase = b * HW;

    #pragma unroll
    for (int cy = 0; cy < 2; ++cy) {
        float yc = y0f + (float)cy;
        if (yc < 0.0f || yc > (float)(H - 1)) continue;
        int yi = (int)yc;
        float wy = cy ? wy1 : wy0;
        float wa = wy * wx0;                  // weight (x0,  yc)
        float wb = wy * wx1;                  // weight (x0+1,yc)
        int q = pbase + yi * W + xi;          // global pixel index of left corner

        if (lo_ok) red_add_f16x2(g_sA + q,     pack2(wa * v0, wa * v1));
        if (hi_ok) red_add_f16x2(g_sA + q + 1, pack2(wb * v0, wb * v1));

        // ch2 into scratchB (half-per-pixel): pair-pack when aligned.
        if (lo_ok && hi_ok && ((q & 1) == 0)) {
            red_add_f16x2(g_sB + (q >> 1), pack2(wa * v2, wb * v2));
        } else {
            __half* hb = reinterpret_cast<__half*>(g_sB);
            if (lo_ok) red_add_f16(hb + q,     __float2half_rn(wa * v2));
            if (hi_ok) red_add_f16(hb + q + 1, __float2half_rn(wb * v2));
        }
    }
}

// ---------------------------------------------------------------------------
// Pass 3: unpack scratch into all three f32 output planes (writes every
// output element; out needs no pre-zeroing). Two pixels per thread.
// ---------------------------------------------------------------------------
__global__ __launch_bounds__(256)
void finalize_kernel(float* __restrict__ out) {
    int j = blockIdx.x * blockDim.x + threadIdx.x;
    constexpr int N2 = NPIX / 2;
    if (j >= N2) return;
    uint2 a = reinterpret_cast<const uint2*>(g_sA)[j];  // pixels 2j, 2j+1
    unsigned int bword = g_sB[j];
    __half2 p0 = *reinterpret_cast<__half2*>(&a.x);     // (ch0,ch1) of 2j
    __half2 p1 = *reinterpret_cast<__half2*>(&a.y);     // (ch0,ch1) of 2j+1
    __half2 c2 = *reinterpret_cast<__half2*>(&bword);   // (ch2 of 2j, ch2 of 2j+1)

    int i = j * 2;
    int b = i / HW;
    int r = i - b * HW;                                  // even
    float* base = out + b * CHW + r;
    *reinterpret_cast<float2*>(base)          = make_float2(__low2float(p0),  __low2float(p1));
    *reinterpret_cast<float2*>(base + HW)     = make_float2(__high2float(p0), __high2float(p1));
    *reinterpret_cast<float2*>(base + 2 * HW) = make_float2(__low2float(c2),  __high2float(c2));
}

extern "C" void kernel_launch(void* const* d_in, const int* in_sizes, int n_in,
                              void* d_out, int out_size) {
    const float*  im0  = (const float*)d_in[0];
    const float2* flow = (const float2*)d_in[1];
    float* out = (float*)d_out;

    int threads = 256;
    constexpr int ZERO_ITEMS = NPIX / 4 + NPIX / 8;
    zero_kernel<<<(ZERO_ITEMS + threads - 1) / threads, threads>>>();
    forward_warp_kernel<<<(NPIX + threads - 1) / threads, threads>>>(im0, flow);
    finalize_kernel<<<(NPIX / 2 + threads - 1) / threads, threads>>>(out);
}

// round 5
// speedup vs baseline: 1.4994x; 1.4994x over previous
#include <cuda_runtime.h>
#include <cuda_fp16.h>
#include <cuda_bf16.h>
#include <cstdint>

// Problem constants (fixed by the reference).
constexpr int B = 8, C = 3, H = 720, W = 1280;
constexpr int HW = H * W;            // 921600
constexpr int NPIX = B * HW;         // 7372800
constexpr int CHW = C * HW;

// Pair-packed scratch: pairs (q,q+1) of destination pixels, banked by q parity.
// Slot s = (q>>1)+1 (pad slot 0 absorbs q=-1 edge). 3 words per slot:
//   w0 = (ch0 of q,   ch1 of q)
//   w1 = (ch2 of q,   ch0 of q+1)
//   w2 = (ch1 of q+1, ch2 of q+1)
constexpr int NPAIR  = NPIX / 2 + 2;   // slots per bank
constexpr int NPAIR3 = NPAIR * 3;      // words per bank
__device__ __align__(16) unsigned int g_bank[2 * NPAIR3];   // ~88.5 MB

__device__ __forceinline__ void red_add_f16x2(unsigned int* p, unsigned int v) {
    asm volatile("red.global.add.noftz.f16x2 [%0], %1;"
                 :: "l"(p), "r"(v) : "memory");
}
__device__ __forceinline__ unsigned int pack2(float a, float b) {
    __half2 h = __floats2half2_rn(a, b);
    return *reinterpret_cast<unsigned int*>(&h);
}
__device__ __forceinline__ float lo_f(unsigned int u) {
    return __low2float(*reinterpret_cast<__half2*>(&u));
}
__device__ __forceinline__ float hi_f(unsigned int u) {
    return __high2float(*reinterpret_cast<__half2*>(&u));
}

// ---------------------------------------------------------------------------
// Pass 1: zero the scratch banks (out is fully overwritten by finalize).
// 2*NPAIR3 = 22,118,412 words, divisible by 4 -> uint4 stores.
// ---------------------------------------------------------------------------
__global__ __launch_bounds__(256)
void zero_kernel() {
    constexpr int N4 = (2 * NPAIR3) / 4;
    int j = blockIdx.x * blockDim.x + threadIdx.x;
    if (j < N4)
        reinterpret_cast<uint4*>(g_bank)[j] = make_uint4(0u, 0u, 0u, 0u);
}

// ---------------------------------------------------------------------------
// Pass 2: forward-warp scatter. Exactly 3 f16x2 REDs per valid corner row
// (6 L2 atomic elements per source pixel). Branchless in x: invalid
// corners contribute weight 0.
// ---------------------------------------------------------------------------
__global__ __launch_bounds__(256)
void forward_warp_kernel(const float* __restrict__ im0,
                         const float2* __restrict__ flow) {
    int p = blockIdx.x * blockDim.x + threadIdx.x;
    if (p >= NPIX) return;

    int b = p / HW;
    int r = p - b * HW;
    int h = r / W;
    int w = r - h * W;

    float2 f = flow[p];
    float x = (float)w + f.x;
    float y = (float)h + f.y;

    float x0f = floorf(x);
    float y0f = floorf(y);
    float wx1 = x - x0f;
    float wx0 = 1.0f - wx1;
    float wy1 = y - y0f;
    float wy0 = 1.0f - wy1;

    int xi = (int)x0f;
    // If both x-corners are out of range, nothing is written at all.
    if (x0f < -1.0f || x0f > (float)(W - 1)) return;
    // Zero the weight of an invalid corner (matches reference's masked add).
    if (x0f < 0.0f)             wx0 = 0.0f;   // xi == -1
    if (x0f > (float)(W - 2))   wx1 = 0.0f;   // xi == W-1

    int ibase = b * CHW + r;
    float v0 = im0[ibase];
    float v1 = im0[ibase + HW];
    float v2 = im0[ibase + 2 * HW];

    int pbase = b * HW;

    #pragma unroll
    for (int cy = 0; cy < 2; ++cy) {
        float yc = y0f + (float)cy;
        if (yc < 0.0f || yc > (float)(H - 1)) continue;
        int yi = (int)yc;
        float wy = cy ? wy1 : wy0;
        float wa = wy * wx0;                 // weight of corner q   (= x0)
        float wb = wy * wx1;                 // weight of corner q+1 (= x0+1)

        int q   = pbase + yi * W + xi;       // in [-1, NPIX-1]
        int par = q & 1;
        int s   = (q >> 1) + 1;              // arithmetic shift: q=-1 -> slot 0
        unsigned int* bp = g_bank + par * NPAIR3 + s * 3;

        red_add_f16x2(bp + 0, pack2(wa * v0, wa * v1));
        red_add_f16x2(bp + 1, pack2(wa * v2, wb * v0));
        red_add_f16x2(bp + 2, pack2(wb * v1, wb * v2));
    }
}

// ---------------------------------------------------------------------------
// Pass 3: gather each pixel's contributions from its two bank pairs and
// write all three f32 planes. Thread j handles pixels i=2j, i+1.
//   pixel i   : left of bank0 slot j+1, right of bank1 slot j
//   pixel i+1 : right of bank0 slot j+1, left of bank1 slot j+1
// ---------------------------------------------------------------------------
__global__ __launch_bounds__(256)
void finalize_kernel(float* __restrict__ out) {
    int j = blockIdx.x * blockDim.x + threadIdx.x;
    constexpr int N2 = NPIX / 2;
    if (j >= N2) return;

    const unsigned int* b0 = g_bank;            // bank 0
    const unsigned int* b1 = g_bank + NPAIR3;   // bank 1

    unsigned int A0 = b0[3 * (j + 1) + 0];
    unsigned int A1 = b0[3 * (j + 1) + 1];
    unsigned int A2 = b0[3 * (j + 1) + 2];
    unsigned int B1 = b1[3 * j + 1];            // bank1 slot j, w1
    unsigned int B2 = b1[3 * j + 2];            // bank1 slot j, w2
    unsigned int B3 = b1[3 * j + 3];            // bank1 slot j+1, w0
    unsigned int B4 = b1[3 * j + 4];            // bank1 slot j+1, w1

    // pixel i = 2j
    float c0a = lo_f(A0) + hi_f(B1);
    float c1a = hi_f(A0) + lo_f(B2);
    float c2a = lo_f(A1) + hi_f(B2);
    // pixel i+1
    float c0b = hi_f(A1) + lo_f(B3);
    float c1b = lo_f(A2) + hi_f(B3);
    float c2b = hi_f(A2) + lo_f(B4);

    int i = j * 2;
    int b = i / HW;
    int r = i - b * HW;                         // even
    float* base = out + b * CHW + r;
    *reinterpret_cast<float2*>(base)          = make_float2(c0a, c0b);
    *reinterpret_cast<float2*>(base + HW)     = make_float2(c1a, c1b);
    *reinterpret_cast<float2*>(base + 2 * HW) = make_float2(c2a, c2b);
}

extern "C" void kernel_launch(void* const* d_in, const int* in_sizes, int n_in,
                              void* d_out, int out_size) {
    const float*  im0  = (const float*)d_in[0];
    const float2* flow = (const float2*)d_in[1];
    float* out = (float*)d_out;

    int threads = 256;
    constexpr int ZERO_ITEMS = (2 * NPAIR3) / 4;
    zero_kernel<<<(ZERO_ITEMS + threads - 1) / threads, threads>>>();
    forward_warp_kernel<<<(NPIX + threads - 1) / threads, threads>>>(im0, flow);
    finalize_kernel<<<(NPIX / 2 + threads - 1) / threads, threads>>>(out);
}

// round 6
// speedup vs baseline: 2.1242x; 1.4167x over previous
#include <cuda_runtime.h>
#include <cuda_fp16.h>
#include <cuda_bf16.h>
#include <cstdint>

// Problem constants (fixed by the reference).
constexpr int B = 8, C = 3, H = 720, W = 1280;
constexpr int HW = H * W;            // 921600
constexpr int NPIX = B * HW;         // 7372800
constexpr int CHW = C * HW;

// sA[pix]  : half2 (ch0, ch1) per destination pixel (R3 layout).  29.5 MB
// sB       : ch2 pair-packed parity banks. Bank0 word k = (ch2[2k], ch2[2k+1]);
//            bank1 word NB+1+k = (ch2[2k+1], ch2[2k+2]), with one pad slot at
//            each bank1 end absorbing the q=-1 / q=NPIX-1 edge pairs. 29.5 MB
constexpr int NB = NPIX / 2 + 1;          // words per bank (bank0 uses NPIX/2)
constexpr int SB_WORDS = 2 * NB + 2;      // rounded up to multiple of 4
__device__ __align__(16) unsigned int g_sA[NPIX];
__device__ __align__(16) unsigned int g_sB[SB_WORDS];

__device__ __forceinline__ void red_add_f16x2(unsigned int* p, unsigned int v) {
    asm volatile("red.global.add.noftz.f16x2 [%0], %1;"
                 :: "l"(p), "r"(v) : "memory");
}
__device__ __forceinline__ unsigned int pack2(float a, float b) {
    __half2 h = __floats2half2_rn(a, b);
    return *reinterpret_cast<unsigned int*>(&h);
}
__device__ __forceinline__ float lo_f(unsigned int u) {
    return __low2float(*reinterpret_cast<__half2*>(&u));
}
__device__ __forceinline__ float hi_f(unsigned int u) {
    return __high2float(*reinterpret_cast<__half2*>(&u));
}

// ---------------------------------------------------------------------------
// Pass 1: zero both scratch regions (out is fully overwritten by finalize).
// ---------------------------------------------------------------------------
__global__ __launch_bounds__(256)
void zero_kernel() {
    constexpr int NA4 = NPIX / 4;
    constexpr int NB4 = SB_WORDS / 4;
    int j = blockIdx.x * blockDim.x + threadIdx.x;
    if (j < NA4) {
        reinterpret_cast<uint4*>(g_sA)[j] = make_uint4(0u, 0u, 0u, 0u);
    } else if (j < NA4 + NB4) {
        reinterpret_cast<uint4*>(g_sB)[j - NA4] = make_uint4(0u, 0u, 0u, 0u);
    }
}

// ---------------------------------------------------------------------------
// Pass 2: forward-warp scatter. Exactly 3 f16x2 REDs per valid corner row,
// uniform across lanes (6 L2 atomic elements per source pixel):
//   sA[q]   += (wa*v0, wa*v1)        (clamped index; +0 when corner invalid)
//   sA[q+1] += (wb*v0, wb*v1)
//   sB[bank(par(q)), slot(q)] += (wa*v2, wb*v2)
// ---------------------------------------------------------------------------
__global__ __launch_bounds__(256)
void forward_warp_kernel(const float* __restrict__ im0,
                         const float2* __restrict__ flow) {
    int p = blockIdx.x * blockDim.x + threadIdx.x;
    if (p >= NPIX) return;

    int b = p / HW;
    int r = p - b * HW;
    int h = r / W;
    int w = r - h * W;

    float2 f = flow[p];
    float x = (float)w + f.x;
    float y = (float)h + f.y;

    float x0f = floorf(x);
    float y0f = floorf(y);
    float wx1 = x - x0f;
    float wx0 = 1.0f - wx1;
    float wy1 = y - y0f;
    float wy0 = 1.0f - wy1;

    int xi = (int)x0f;
    if (x0f < -1.0f || x0f > (float)(W - 1)) return;   // both x-corners OOB
    if (x0f < 0.0f)           wx0 = 0.0f;              // xi == -1
    if (x0f > (float)(W - 2)) wx1 = 0.0f;              // xi == W-1

    int ibase = b * CHW + r;
    float v0 = im0[ibase];
    float v1 = im0[ibase + HW];
    float v2 = im0[ibase + 2 * HW];

    int pbase = b * HW;

    #pragma unroll
    for (int cy = 0; cy < 2; ++cy) {
        float yc = y0f + (float)cy;
        if (yc < 0.0f || yc > (float)(H - 1)) continue;
        int yi = (int)yc;
        float wy = cy ? wy1 : wy0;
        float wa = wy * wx0;                 // weight of corner q   (= x0)
        float wb = wy * wx1;                 // weight of corner q+1 (= x0+1)

        int q  = pbase + yi * W + xi;        // in [-1, NPIX-1]
        int qa = max(q, 0);                  // clamped: wa==0 when clamp fires
        int qb = min(q + 1, NPIX - 1);       // clamped: wb==0 when clamp fires

        red_add_f16x2(g_sA + qa, pack2(wa * v0, wa * v1));
        red_add_f16x2(g_sA + qb, pack2(wb * v0, wb * v1));

        // ch2 pair word: bank by parity of q; slot covers (q:lo, q+1:hi).
        int par = q & 1;                     // q=-1 -> par=1
        int off = par * (NB + 1) + (q >> 1) + par;  // bank0: q/2 ; bank1: NB+1+(q>>1)+1
        red_add_f16x2(g_sB + off, pack2(wa * v2, wb * v2));
    }
}

// ---------------------------------------------------------------------------
// Pass 3: gather and write all three f32 planes. Thread j -> pixels 2j, 2j+1.
//   ch2[2j]   = lo(bank0[j])  + hi(bank1[NB+1 + j])
//   ch2[2j+1] = hi(bank0[j])  + lo(bank1[NB+1 + j + 1])
// ---------------------------------------------------------------------------
__global__ __launch_bounds__(256)
void finalize_kernel(float* __restrict__ out) {
    int j = blockIdx.x * blockDim.x + threadIdx.x;
    constexpr int N2 = NPIX / 2;
    if (j >= N2) return;

    uint2 a = reinterpret_cast<const uint2*>(g_sA)[j];   // sA of pixels 2j,2j+1
    unsigned int w0 = g_sB[j];                           // bank0 slot j
    unsigned int w1 = g_sB[NB + 1 + j];                  // bank1 slot j
    unsigned int w2 = g_sB[NB + 1 + j + 1];              // bank1 slot j+1

    __half2 p0 = *reinterpret_cast<__half2*>(&a.x);
    __half2 p1 = *reinterpret_cast<__half2*>(&a.y);

    float c0a = __low2float(p0);
    float c1a = __high2float(p0);
    float c0b = __low2float(p1);
    float c1b = __high2float(p1);
    float c2a = lo_f(w0) + hi_f(w1);
    float c2b = hi_f(w0) + lo_f(w2);

    int i = j * 2;
    int b = i / HW;
    int r = i - b * HW;                                  // even
    float* base = out + b * CHW + r;
    *reinterpret_cast<float2*>(base)          = make_float2(c0a, c0b);
    *reinterpret_cast<float2*>(base + HW)     = make_float2(c1a, c1b);
    *reinterpret_cast<float2*>(base + 2 * HW) = make_float2(c2a, c2b);
}

extern "C" void kernel_launch(void* const* d_in, const int* in_sizes, int n_in,
                              void* d_out, int out_size) {
    const float*  im0  = (const float*)d_in[0];
    const float2* flow = (const float2*)d_in[1];
    float* out = (float*)d_out;

    int threads = 256;
    constexpr int ZERO_ITEMS = NPIX / 4 + SB_WORDS / 4;
    zero_kernel<<<(ZERO_ITEMS + threads - 1) / threads, threads>>>();
    forward_warp_kernel<<<(NPIX + threads - 1) / threads, threads>>>(im0, flow);
    finalize_kernel<<<(NPIX / 2 + threads - 1) / threads, threads>>>(out);
}